// round 8
// baseline (speedup 1.0000x reference)
#include <cuda_runtime.h>
#include <cuda_fp16.h>
#include <math.h>

#define BATCH 32
#define H 512
#define W 512
#define HW (H*W)
#define NTOT (BATCH*HW)
#define KRAD 15
#define KK_INV (1.0f/961.0f)

#define ROWS_PB 32
#define NSLOT 40
#define NWARP 8
#define NTHR 256
#define NBLK (BATCH * (H / ROWS_PB))      // 512
#define CHUNKS_PER_IMG (H / ROWS_PB)      // 16

// dynamic smem layout (bytes)
#define CB_BYTES   (NSLOT * W * 2)        // 40960
#define PSCR_BYTES (NWARP * W * 4)        // 16384
#define SMEM_TOTAL (CB_BYTES + PSCR_BYTES + NTHR * 4 * 4)   // + red = 61440

__device__ float g_part[NBLK][4];         // {bce, wsum, inter, union}
__device__ unsigned g_done = 0;

__device__ __forceinline__ int slotof(int row) {
    return (unsigned)(row + 80) % NSLOT;
}

// Warp computes the 31-wide horizontal box sum of one targ row into an fp16
// ring row. Rows outside [0,H) are zero-filled.
__device__ __forceinline__ void compute_hsum_row(
    const float* __restrict__ tb, int row, float* Pw, __half* cbrow, int lane) {
    uint2* cb2 = (uint2*)cbrow;
    if (row < 0 || row >= H) {
        #pragma unroll
        for (int c = 0; c < 4; ++c) cb2[c * 32 + lane] = make_uint2(0u, 0u);
        return;
    }
    const unsigned FULL = 0xffffffffu;
    const float4* __restrict__ rowp = (const float4*)(tb + (size_t)row * W);
    float4* P4 = (float4*)Pw;

    float carry = 0.0f;
    #pragma unroll
    for (int c = 0; c < 4; ++c) {
        float4 q = rowp[c * 32 + lane];
        float p0 = q.x;
        float p1 = p0 + q.y;
        float p2 = p1 + q.z;
        float p3 = p2 + q.w;
        float s = p3;
        #pragma unroll
        for (int off = 1; off < 32; off <<= 1) {
            float n = __shfl_up_sync(FULL, s, off);
            if (lane >= off) s += n;
        }
        const float base = s - p3 + carry;
        P4[c * 32 + lane] = make_float4(base + p0, base + p1, base + p2, base + p3);
        carry += __shfl_sync(FULL, s, 31);
    }
    __syncwarp();
    const float total = carry;
    #pragma unroll
    for (int c = 0; c < 4; ++c) {
        const int g = c * 32 + lane;
        float4 A;
        if (g < 124) {
            float4 Q1 = P4[g + 3];
            float4 Q2 = P4[g + 4];
            A = make_float4(Q1.w, Q2.x, Q2.y, Q2.z);
        } else {
            A = make_float4(total, total, total, total);
        }
        float4 B = (g >= 4) ? P4[g - 4] : make_float4(0.f, 0.f, 0.f, 0.f);
        __half2 ha = __floats2half2_rn(A.x - B.x, A.y - B.y);
        __half2 hb = __floats2half2_rn(A.z - B.z, A.w - B.w);
        uint2 u;
        u.x = *reinterpret_cast<unsigned*>(&ha);
        u.y = *reinterpret_cast<unsigned*>(&hb);
        cb2[g] = u;
    }
}

__device__ __forceinline__ void lane_math(float xv, float tv, float vsum,
                                          float& bce, float& ws, float& it, float& un) {
    const float w   = fmaf(5.0f, fabsf(vsum * KK_INV - tv), 1.0f);
    const float E   = __expf(-fabsf(xv));
    const float u   = 1.0f + E;
    const float sp  = fmaxf(xv, 0.0f) + __logf(u);
    const float inv = __fdividef(1.0f, u);
    const float p   = (xv >= 0.0f) ? inv : E * inv;
    bce += sp - xv * tv;
    ws  += w;
    it  += p * tv * w;
    un  += (p + tv) * w;
}

// ---------------------------------------------------------------------------
// Fused kernel: grid (16, 32), block 256 (8 warps).
// Each group: 8 warps produce 8 hsum ring rows in parallel, then all 256
// threads (2 cols each) run 8 rows of sliding-window + loss math.
// Last finished block performs the global finalize.
// ---------------------------------------------------------------------------
extern __shared__ char smem_raw[];

__global__ __launch_bounds__(NTHR) void fused_kernel(const float* __restrict__ pred,
                                                     const float* __restrict__ targ,
                                                     float* __restrict__ out) {
    __half* CB   = (__half*)smem_raw;                       // [NSLOT][W]
    float*  Pscr = (float*)(smem_raw + CB_BYTES);           // [NWARP][W]
    float*  red  = (float*)(smem_raw + CB_BYTES + PSCR_BYTES); // [4][NTHR]

    const int b    = blockIdx.y;
    const int tid  = threadIdx.x;
    const int w    = tid >> 5;
    const int lane = tid & 31;
    const int r0   = blockIdx.x * ROWS_PB;

    const float* __restrict__ tb = targ + (size_t)b * HW;
    const float* __restrict__ pb = pred + (size_t)b * HW;
    const float2* __restrict__ tb2 = (const float2*)tb;
    const float2* __restrict__ pb2 = (const float2*)pb;

    // Prologue: hsum rows r0-15 .. r0+15 (31 rows, 8 warps, 4 rounds)
    #pragma unroll
    for (int k = 0; k < 4; ++k) {
        const int i = k * 8 + w;
        if (i < 31) {
            const int row = r0 - 15 + i;
            compute_hsum_row(tb, row, Pscr + w * W, CB + slotof(row) * W, lane);
        }
    }
    __syncthreads();

    // Initial vertical window (2 cols per thread)
    float vx = 0.f, vy = 0.f;
    #pragma unroll
    for (int i = 0; i < 31; ++i) {
        const int row = r0 - 15 + i;
        unsigned u = ((unsigned*)(CB + slotof(row) * W))[tid];
        float2 a = __half22float2(*reinterpret_cast<__half2*>(&u));
        vx += a.x; vy += a.y;
    }

    float bce_a = 0.f, wsum_a = 0.f, inter_a = 0.f, uni_a = 0.f;

    #pragma unroll
    for (int gr = 0; gr < ROWS_PB / 8; ++gr) {
        const int r = r0 + gr * 8;
        // Produce rows r+16 .. r+23, one per warp
        {
            const int row = r + 16 + w;
            compute_hsum_row(tb, row, Pscr + w * W, CB + slotof(row) * W, lane);
        }
        __syncthreads();

        #pragma unroll
        for (int j = 0; j < 8; ++j) {
            const int rr = r + j;
            const float2 tv = tb2[rr * (W/2) + tid];
            const float2 xv = pb2[rr * (W/2) + tid];

            lane_math(xv.x, tv.x, vx, bce_a, wsum_a, inter_a, uni_a);
            lane_math(xv.y, tv.y, vy, bce_a, wsum_a, inter_a, uni_a);

            // slide: add row rr+16, subtract row rr-15
            unsigned ua = ((unsigned*)(CB + slotof(rr + 16) * W))[tid];
            unsigned us = ((unsigned*)(CB + slotof(rr - 15) * W))[tid];
            float2 aa = __half22float2(*reinterpret_cast<__half2*>(&ua));
            float2 sa = __half22float2(*reinterpret_cast<__half2*>(&us));
            vx += aa.x - sa.x;
            vy += aa.y - sa.y;
        }
        __syncthreads();   // ring slots free before next produce
    }

    // Deterministic block reduction (fixed order)
    red[0 * NTHR + tid] = bce_a;
    red[1 * NTHR + tid] = wsum_a;
    red[2 * NTHR + tid] = inter_a;
    red[3 * NTHR + tid] = uni_a;
    __syncthreads();
    #pragma unroll
    for (int off = NTHR / 2; off > 0; off >>= 1) {
        if (tid < off) {
            red[0 * NTHR + tid] += red[0 * NTHR + tid + off];
            red[1 * NTHR + tid] += red[1 * NTHR + tid + off];
            red[2 * NTHR + tid] += red[2 * NTHR + tid + off];
            red[3 * NTHR + tid] += red[3 * NTHR + tid + off];
        }
        __syncthreads();
    }

    __shared__ unsigned last_flag;
    if (tid == 0) {
        const int blin = b * gridDim.x + blockIdx.x;   // image-major
        g_part[blin][0] = red[0 * NTHR];
        g_part[blin][1] = red[1 * NTHR];
        g_part[blin][2] = red[2 * NTHR];
        g_part[blin][3] = red[3 * NTHR];
        __threadfence();
        last_flag = (atomicAdd(&g_done, 1u) == NBLK - 1u);
    }
    __syncthreads();
    if (!last_flag) return;

    // ---- Last block: global finalize (fixed-order sums) ----
    __threadfence();
    if (tid == 0) g_done = 0;   // reset for next graph replay

    float acc = 0.0f;
    #pragma unroll
    for (int j = 0; j < NBLK / NTHR; ++j) acc += g_part[tid * (NBLK / NTHR) + j][0];
    red[tid] = acc;
    __syncthreads();
    #pragma unroll
    for (int off = NTHR / 2; off > 0; off >>= 1) {
        if (tid < off) red[tid] += red[tid + off];
        __syncthreads();
    }
    const float bce = red[0] * (1.0f / (float)NTOT);
    __syncthreads();

    if (tid < BATCH) {
        float ws = 0.0f, it = 0.0f, un = 0.0f;
        #pragma unroll
        for (int j = 0; j < CHUNKS_PER_IMG; ++j) {
            const int bl = tid * CHUNKS_PER_IMG + j;
            ws += g_part[bl][1];
            it += g_part[bl][2];
            un += g_part[bl][3];
        }
        const float w_bce = (ws * bce + 1e-8f) / (ws + 1e-8f);
        const float w_iou = 1.0f - (it + 1.0f + 1e-8f) / (un - it + 1.0f + 1e-8f);
        red[tid] = w_bce + w_iou;
    }
    __syncthreads();
    if (tid == 0) {
        float a = 0.0f;
        #pragma unroll
        for (int i = 0; i < BATCH; ++i) a += red[i];
        out[0] = a * (1.0f / (float)BATCH);
    }
}

// ---------------------------------------------------------------------------
extern "C" void kernel_launch(void* const* d_in, const int* in_sizes, int n_in,
                              void* d_out, int out_size) {
    const float* y_pred   = (const float*)d_in[0];
    const float* y_target = (const float*)d_in[1];
    float* out = (float*)d_out;

    cudaFuncSetAttribute(fused_kernel, cudaFuncAttributeMaxDynamicSharedMemorySize,
                         SMEM_TOTAL);

    dim3 g(H / ROWS_PB, BATCH);       // (16, 32) = 512 blocks
    fused_kernel<<<g, NTHR, SMEM_TOTAL>>>(y_pred, y_target, out);
}

// round 9
// speedup vs baseline: 1.2462x; 1.2462x over previous
#include <cuda_runtime.h>
#include <cuda_fp16.h>
#include <math.h>

#define BATCH 32
#define H 512
#define W 512
#define HW (H*W)
#define NTOT (BATCH*HW)
#define KRAD 15
#define KK_INV (1.0f/961.0f)

#define ROWS_PB 32
#define NSLOT 40
#define NWARP 4
#define NTHR 128
#define NBLK (BATCH * (H / ROWS_PB))      // 512
#define CHUNKS_PER_IMG (H / ROWS_PB)      // 16

// dynamic smem layout (bytes)
#define CB_BYTES   (NSLOT * W * 2)        // 40960
#define PSCR_BYTES (NWARP * W * 4)        // 8192
#define RED_BYTES  (4 * NTHR * 4)         // 2048
#define SMEM_TOTAL (CB_BYTES + PSCR_BYTES + RED_BYTES)   // 51200

__device__ float g_part[NBLK][4];         // {bce, wsum, inter, union}
__device__ unsigned g_done = 0;

__device__ __forceinline__ int slotof(int row) {
    return (unsigned)(row + 80) % NSLOT;
}

// Warp computes the 31-wide horizontal box sum of one targ row into an fp16
// ring row. Rows outside [0,H) are zero-filled.
__device__ __forceinline__ void compute_hsum_row(
    const float* __restrict__ tb, int row, float* Pw, __half* cbrow, int lane) {
    uint2* cb2 = (uint2*)cbrow;
    if (row < 0 || row >= H) {
        #pragma unroll
        for (int c = 0; c < 4; ++c) cb2[c * 32 + lane] = make_uint2(0u, 0u);
        return;
    }
    const unsigned FULL = 0xffffffffu;
    const float4* __restrict__ rowp = (const float4*)(tb + (size_t)row * W);
    float4* P4 = (float4*)Pw;

    float carry = 0.0f;
    #pragma unroll
    for (int c = 0; c < 4; ++c) {
        float4 q = rowp[c * 32 + lane];
        float p0 = q.x;
        float p1 = p0 + q.y;
        float p2 = p1 + q.z;
        float p3 = p2 + q.w;
        float s = p3;
        #pragma unroll
        for (int off = 1; off < 32; off <<= 1) {
            float n = __shfl_up_sync(FULL, s, off);
            if (lane >= off) s += n;
        }
        const float base = s - p3 + carry;
        P4[c * 32 + lane] = make_float4(base + p0, base + p1, base + p2, base + p3);
        carry += __shfl_sync(FULL, s, 31);
    }
    __syncwarp();
    const float total = carry;
    #pragma unroll
    for (int c = 0; c < 4; ++c) {
        const int g = c * 32 + lane;
        float4 A;
        if (g < 124) {
            float4 Q1 = P4[g + 3];
            float4 Q2 = P4[g + 4];
            A = make_float4(Q1.w, Q2.x, Q2.y, Q2.z);
        } else {
            A = make_float4(total, total, total, total);
        }
        float4 B = (g >= 4) ? P4[g - 4] : make_float4(0.f, 0.f, 0.f, 0.f);
        __half2 ha = __floats2half2_rn(A.x - B.x, A.y - B.y);
        __half2 hb = __floats2half2_rn(A.z - B.z, A.w - B.w);
        uint2 u;
        u.x = *reinterpret_cast<unsigned*>(&ha);
        u.y = *reinterpret_cast<unsigned*>(&hb);
        cb2[g] = u;
    }
}

__device__ __forceinline__ void lane_math(float xv, float tv, float vsum,
                                          float& bce, float& ws, float& it, float& un) {
    const float w   = fmaf(5.0f, fabsf(vsum * KK_INV - tv), 1.0f);
    const float E   = __expf(-fabsf(xv));
    const float u   = 1.0f + E;
    const float sp  = fmaxf(xv, 0.0f) + __logf(u);
    const float inv = __fdividef(1.0f, u);
    const float p   = (xv >= 0.0f) ? inv : E * inv;
    bce += sp - xv * tv;
    ws  += w;
    it  += p * tv * w;
    un  += (p + tv) * w;
}

// ---------------------------------------------------------------------------
// Fused kernel: grid (16, 32), block 128 (4 warps).
// Per group: 4 warps produce 8 hsum ring rows (2 each), then all 128 threads
// (4 cols each) run 8 rows of sliding-window + loss math. Last block finalizes.
// ---------------------------------------------------------------------------
extern __shared__ char smem_raw[];

__global__ __launch_bounds__(NTHR) void fused_kernel(const float* __restrict__ pred,
                                                     const float* __restrict__ targ,
                                                     float* __restrict__ out) {
    __half* CB   = (__half*)smem_raw;                            // [NSLOT][W]
    float*  Pscr = (float*)(smem_raw + CB_BYTES);                // [NWARP][W]
    float*  red  = (float*)(smem_raw + CB_BYTES + PSCR_BYTES);   // [4][NTHR]

    const int b    = blockIdx.y;
    const int tid  = threadIdx.x;
    const int w    = tid >> 5;
    const int lane = tid & 31;
    const int r0   = blockIdx.x * ROWS_PB;

    const float* __restrict__ tb = targ + (size_t)b * HW;
    const float* __restrict__ pb = pred + (size_t)b * HW;
    const float4* __restrict__ tb4 = (const float4*)tb;
    const float4* __restrict__ pb4 = (const float4*)pb;

    // Prologue: hsum rows r0-15 .. r0+15 (31 rows, 4 warps, 8 rounds)
    #pragma unroll
    for (int k = 0; k < 8; ++k) {
        const int i = k * 4 + w;
        if (i < 31) {
            const int row = r0 - 15 + i;
            compute_hsum_row(tb, row, Pscr + w * W, CB + slotof(row) * W, lane);
        }
    }
    __syncthreads();

    // Initial vertical window (4 cols per thread)
    float4 vs = make_float4(0.f, 0.f, 0.f, 0.f);
    #pragma unroll
    for (int i = 0; i < 31; ++i) {
        const int row = r0 - 15 + i;
        uint2 u = ((uint2*)(CB + slotof(row) * W))[tid];
        float2 a = __half22float2(*reinterpret_cast<__half2*>(&u.x));
        float2 c = __half22float2(*reinterpret_cast<__half2*>(&u.y));
        vs.x += a.x; vs.y += a.y; vs.z += c.x; vs.w += c.y;
    }

    float bce_a = 0.f, wsum_a = 0.f, inter_a = 0.f, uni_a = 0.f;

    #pragma unroll
    for (int gr = 0; gr < ROWS_PB / 8; ++gr) {
        const int r = r0 + gr * 8;
        // Produce rows r+16 .. r+23: warp w does rows r+16+w and r+20+w
        compute_hsum_row(tb, r + 16 + w, Pscr + w * W, CB + slotof(r + 16 + w) * W, lane);
        compute_hsum_row(tb, r + 20 + w, Pscr + w * W, CB + slotof(r + 20 + w) * W, lane);
        __syncthreads();

        #pragma unroll
        for (int j = 0; j < 8; ++j) {
            const int rr = r + j;
            const float4 tv = tb4[rr * (W/4) + tid];
            const float4 xv = pb4[rr * (W/4) + tid];

            lane_math(xv.x, tv.x, vs.x, bce_a, wsum_a, inter_a, uni_a);
            lane_math(xv.y, tv.y, vs.y, bce_a, wsum_a, inter_a, uni_a);
            lane_math(xv.z, tv.z, vs.z, bce_a, wsum_a, inter_a, uni_a);
            lane_math(xv.w, tv.w, vs.w, bce_a, wsum_a, inter_a, uni_a);

            // slide: add row rr+16, subtract row rr-15
            uint2 ua = ((uint2*)(CB + slotof(rr + 16) * W))[tid];
            uint2 us = ((uint2*)(CB + slotof(rr - 15) * W))[tid];
            float2 aa = __half22float2(*reinterpret_cast<__half2*>(&ua.x));
            float2 ab = __half22float2(*reinterpret_cast<__half2*>(&ua.y));
            float2 sa = __half22float2(*reinterpret_cast<__half2*>(&us.x));
            float2 sb = __half22float2(*reinterpret_cast<__half2*>(&us.y));
            vs.x += aa.x - sa.x;
            vs.y += aa.y - sa.y;
            vs.z += ab.x - sb.x;
            vs.w += ab.y - sb.y;
        }
        __syncthreads();   // ring slots free before next produce
    }

    // Deterministic block reduction (fixed order)
    red[0 * NTHR + tid] = bce_a;
    red[1 * NTHR + tid] = wsum_a;
    red[2 * NTHR + tid] = inter_a;
    red[3 * NTHR + tid] = uni_a;
    __syncthreads();
    #pragma unroll
    for (int off = NTHR / 2; off > 0; off >>= 1) {
        if (tid < off) {
            red[0 * NTHR + tid] += red[0 * NTHR + tid + off];
            red[1 * NTHR + tid] += red[1 * NTHR + tid + off];
            red[2 * NTHR + tid] += red[2 * NTHR + tid + off];
            red[3 * NTHR + tid] += red[3 * NTHR + tid + off];
        }
        __syncthreads();
    }

    __shared__ unsigned last_flag;
    if (tid == 0) {
        const int blin = b * gridDim.x + blockIdx.x;   // image-major
        g_part[blin][0] = red[0 * NTHR];
        g_part[blin][1] = red[1 * NTHR];
        g_part[blin][2] = red[2 * NTHR];
        g_part[blin][3] = red[3 * NTHR];
        __threadfence();
        last_flag = (atomicAdd(&g_done, 1u) == NBLK - 1u);
    }
    __syncthreads();
    if (!last_flag) return;

    // ---- Last block: global finalize (fixed-order sums) ----
    __threadfence();
    if (tid == 0) g_done = 0;   // reset for next graph replay

    float acc = 0.0f;
    #pragma unroll
    for (int j = 0; j < NBLK / NTHR; ++j) acc += g_part[tid * (NBLK / NTHR) + j][0];
    red[tid] = acc;
    __syncthreads();
    #pragma unroll
    for (int off = NTHR / 2; off > 0; off >>= 1) {
        if (tid < off) red[tid] += red[tid + off];
        __syncthreads();
    }
    const float bce = red[0] * (1.0f / (float)NTOT);
    __syncthreads();

    if (tid < BATCH) {
        float ws = 0.0f, it = 0.0f, un = 0.0f;
        #pragma unroll
        for (int j = 0; j < CHUNKS_PER_IMG; ++j) {
            const int bl = tid * CHUNKS_PER_IMG + j;
            ws += g_part[bl][1];
            it += g_part[bl][2];
            un += g_part[bl][3];
        }
        const float w_bce = (ws * bce + 1e-8f) / (ws + 1e-8f);
        const float w_iou = 1.0f - (it + 1.0f + 1e-8f) / (un - it + 1.0f + 1e-8f);
        red[tid] = w_bce + w_iou;
    }
    __syncthreads();
    if (tid == 0) {
        float a = 0.0f;
        #pragma unroll
        for (int i = 0; i < BATCH; ++i) a += red[i];
        out[0] = a * (1.0f / (float)BATCH);
    }
}

// ---------------------------------------------------------------------------
extern "C" void kernel_launch(void* const* d_in, const int* in_sizes, int n_in,
                              void* d_out, int out_size) {
    const float* y_pred   = (const float*)d_in[0];
    const float* y_target = (const float*)d_in[1];
    float* out = (float*)d_out;

    cudaFuncSetAttribute(fused_kernel, cudaFuncAttributeMaxDynamicSharedMemorySize,
                         SMEM_TOTAL);

    dim3 g(H / ROWS_PB, BATCH);       // (16, 32) = 512 blocks
    fused_kernel<<<g, NTHR, SMEM_TOTAL>>>(y_pred, y_target, out);
}